// round 11
// baseline (speedup 1.0000x reference)
#include <cuda_runtime.h>
#include <cuda_bf16.h>

#define TAGS 128
typedef __nv_bfloat162 bf2;

__global__ void __launch_bounds__(TAGS, 1) crf_logz_kernel(
    const float* __restrict__ emissions,     // [B, T, 1, TAGS]
    const int*   __restrict__ token_sizes,   // [B]
    const float* __restrict__ transitions,   // [1, 1, TAGS, TAGS]
    const float* __restrict__ head_t,        // [1, 1, TAGS]
    const float* __restrict__ last_t,        // [1, 1, TAGS]
    float*       __restrict__ out,           // [B, 1]
    int T)
{
    __shared__ __align__(16) __nv_bfloat16 pbuf[2][TAGS];
    __shared__ float wsum[4];

    const int n = threadIdx.x;      // output tag owned by this thread
    const int b = blockIdx.x;       // batch element owned by this CTA
    const int len = token_sizes[b];
    const int Tm1 = T - 1;
    const float* emb = emissions + (size_t)b * T * TAGS;

    // exp(transitions) column n as bf16x2 pairs: T2[i] = (T[2i,n], T[2i+1,n]).
    bf2 T2[TAGS / 2];
#pragma unroll
    for (int i = 0; i < TAGS / 2; ++i)
        T2[i] = __floats2bfloat162_rn(__expf(transitions[(2 * i    ) * TAGS + n]),
                                      __expf(transitions[(2 * i + 1) * TAGS + n]));

    // alpha_0 = head + emissions[0]  ->  p = exp(alpha)  (bf16 storage)
    pbuf[0][n] = __float2bfloat16(__expf(head_t[n] + emb[n]));
    int etot = 0;        // exact integer sum of stripped binary exponents
    int fb = 0;          // live buffer for the tail bookkeeping

// Step body (barrier issued separately so independent work can ride the
// DEFER_BLOCKING window between BAR and the first LDS).
// 64 HFMA2 (rt=2) = 128 cyc fma pacing; 2 accumulators (reissue spacing
// 4 cyc = HFMA2 lat, stall-free) -> 1-level reduce. Scale applied before
// the lo/hi fold. p[0]'s exponent comes from the first matvec load.
#define STEP_BODY(SRC, DST, EV) do {                                       \
    const uint4* _pd = reinterpret_cast<const uint4*>(&pbuf[SRC][0]);      \
    uint4 _q0 = _pd[0];                                                    \
    int _e = (int)((_q0.x >> 7) & 255) - 127;      /* bf16 exp of p[0] */  \
    float _sc = __int_as_float((127 - _e) << 23);                          \
    bf2 _Es = __float2bfloat162_rn((EV) * _sc);                            \
    bf2 _h0 = __float2bfloat162_rn(0.0f);                                  \
    bf2 _h1 = _h0;                                                         \
    _h0 = __hfma2(*reinterpret_cast<bf2*>(&_q0.x), T2[0], _h0);            \
    _h1 = __hfma2(*reinterpret_cast<bf2*>(&_q0.y), T2[1], _h1);            \
    _h0 = __hfma2(*reinterpret_cast<bf2*>(&_q0.z), T2[2], _h0);            \
    _h1 = __hfma2(*reinterpret_cast<bf2*>(&_q0.w), T2[3], _h1);            \
    _Pragma("unroll")                                                      \
    for (int _i = 1; _i < 16; ++_i) {                                      \
        uint4 _q = _pd[_i];                        /* 8 p-halves */        \
        _h0 = __hfma2(*reinterpret_cast<bf2*>(&_q.x), T2[4 * _i    ], _h0);\
        _h1 = __hfma2(*reinterpret_cast<bf2*>(&_q.y), T2[4 * _i + 1], _h1);\
        _h0 = __hfma2(*reinterpret_cast<bf2*>(&_q.z), T2[4 * _i + 2], _h0);\
        _h1 = __hfma2(*reinterpret_cast<bf2*>(&_q.w), T2[4 * _i + 3], _h1);\
    }                                                                      \
    bf2 _s = __hadd2(_h0, _h1);                                            \
    bf2 _v = __hmul2(_s, _Es);                     /* scale both lanes */  \
    bf2 _pn = __hadd2(_v, __lowhigh2highlow(_v));  /* lo+hi fold */        \
    pbuf[DST][n] = __low2bfloat16(_pn);                                    \
    etot += _e;                                                            \
} while (0)

#define STEP(SRC, DST, EV) do { __syncthreads(); STEP_BODY(SRC, DST, EV); } while (0)

    // Two-stage emission prefetch, unroll 8:
    //   E0..E7: exp()'d emissions for steps t..t+7
    //   Q0..Q7: raw emissions for steps t+8..t+15 (LDG distance 16)
    // Each step slot does ONE LDG and ONE expf in the post-barrier
    // deferred-blocking window (free during barrier wait).
    int t = 1;
    float E0 = __expf(emb[min(1, Tm1) * TAGS + n]);
    float E1 = __expf(emb[min(2, Tm1) * TAGS + n]);
    float E2 = __expf(emb[min(3, Tm1) * TAGS + n]);
    float E3 = __expf(emb[min(4, Tm1) * TAGS + n]);
    float E4 = __expf(emb[min(5, Tm1) * TAGS + n]);
    float E5 = __expf(emb[min(6, Tm1) * TAGS + n]);
    float E6 = __expf(emb[min(7, Tm1) * TAGS + n]);
    float E7 = __expf(emb[min(8, Tm1) * TAGS + n]);
    float Q0 = emb[min( 9, Tm1) * TAGS + n];
    float Q1 = emb[min(10, Tm1) * TAGS + n];
    float Q2 = emb[min(11, Tm1) * TAGS + n];
    float Q3 = emb[min(12, Tm1) * TAGS + n];
    float Q4 = emb[min(13, Tm1) * TAGS + n];
    float Q5 = emb[min(14, Tm1) * TAGS + n];
    float Q6 = emb[min(15, Tm1) * TAGS + n];
    float Q7 = emb[min(16, Tm1) * TAGS + n];

    // Fast loop: t+24 <= len implies prefetch rows t+16..t+23 < T: no clamps.
    for (; t + 24 <= len; t += 8) {
        const float* ep = emb + (size_t)(t + 16) * TAGS + n;
        float R0, R1, R2, R3, R4, R5, R6, R7;
        __syncthreads(); R0 = ep[0];
        STEP_BODY(0, 1, E0);
        __syncthreads(); R1 = ep[    TAGS]; E0 = __expf(Q0); Q0 = R0;
        STEP_BODY(1, 0, E1);
        __syncthreads(); R2 = ep[2 * TAGS]; E1 = __expf(Q1); Q1 = R1;
        STEP_BODY(0, 1, E2);
        __syncthreads(); R3 = ep[3 * TAGS]; E2 = __expf(Q2); Q2 = R2;
        STEP_BODY(1, 0, E3);
        __syncthreads(); R4 = ep[4 * TAGS]; E3 = __expf(Q3); Q3 = R3;
        STEP_BODY(0, 1, E4);
        __syncthreads(); R5 = ep[5 * TAGS]; E4 = __expf(Q4); Q4 = R4;
        STEP_BODY(1, 0, E5);
        __syncthreads(); R6 = ep[6 * TAGS]; E5 = __expf(Q5); Q5 = R5;
        STEP_BODY(0, 1, E6);
        __syncthreads(); R7 = ep[7 * TAGS]; E6 = __expf(Q6); Q6 = R6;
        STEP_BODY(1, 0, E7);
        E7 = __expf(Q7); Q7 = R7;
    }
    // Clamped boundary loop (few iterations; same slot structure).
    for (; t + 8 <= len; t += 8) {
        int tp = t + 16;
        float R0, R1, R2, R3, R4, R5, R6, R7;
        __syncthreads(); R0 = emb[min(tp,     Tm1) * TAGS + n];
        STEP_BODY(0, 1, E0);
        __syncthreads(); R1 = emb[min(tp + 1, Tm1) * TAGS + n]; E0 = __expf(Q0); Q0 = R0;
        STEP_BODY(1, 0, E1);
        __syncthreads(); R2 = emb[min(tp + 2, Tm1) * TAGS + n]; E1 = __expf(Q1); Q1 = R1;
        STEP_BODY(0, 1, E2);
        __syncthreads(); R3 = emb[min(tp + 3, Tm1) * TAGS + n]; E2 = __expf(Q2); Q2 = R2;
        STEP_BODY(1, 0, E3);
        __syncthreads(); R4 = emb[min(tp + 4, Tm1) * TAGS + n]; E3 = __expf(Q3); Q3 = R3;
        STEP_BODY(0, 1, E4);
        __syncthreads(); R5 = emb[min(tp + 5, Tm1) * TAGS + n]; E4 = __expf(Q4); Q4 = R4;
        STEP_BODY(1, 0, E5);
        __syncthreads(); R6 = emb[min(tp + 6, Tm1) * TAGS + n]; E5 = __expf(Q5); Q5 = R5;
        STEP_BODY(0, 1, E6);
        __syncthreads(); R7 = emb[min(tp + 7, Tm1) * TAGS + n]; E6 = __expf(Q6); Q6 = R6;
        STEP_BODY(1, 0, E7);
        E7 = __expf(Q7); Q7 = R7;
    }
    // Tail (0-7 steps); E0..E6 already exp()'d.
    if (t < len) { STEP(0, 1, E0); fb = 1; ++t; }
    if (t < len) { STEP(1, 0, E1); fb = 0; ++t; }
    if (t < len) { STEP(0, 1, E2); fb = 1; ++t; }
    if (t < len) { STEP(1, 0, E3); fb = 0; ++t; }
    if (t < len) { STEP(0, 1, E4); fb = 1; ++t; }
    if (t < len) { STEP(1, 0, E5); fb = 0; ++t; }
    if (t < len) { STEP(0, 1, E6); fb = 1; ++t; }

    // Finalize: out[b] = etot*ln2 + log( sum_n p[n] * exp(last[n]) )  (fp32)
    __syncthreads();
    float v = __bfloat162float(pbuf[fb][n]) * __expf(last_t[n]);
#pragma unroll
    for (int sft = 16; sft > 0; sft >>= 1)
        v += __shfl_xor_sync(0xffffffffu, v, sft);
    if ((n & 31) == 0) wsum[n >> 5] = v;
    __syncthreads();
    if (n == 0)
        out[b] = (float)((double)etot * 0.6931471805599453 +
                         (double)__logf(wsum[0] + wsum[1] + wsum[2] + wsum[3]));
}

extern "C" void kernel_launch(void* const* d_in, const int* in_sizes, int n_in,
                              void* d_out, int out_size) {
    const float* em = (const float*)d_in[0];
    const int*   ts = (const int*)  d_in[1];
    const float* tr = (const float*)d_in[2];
    const float* hd = (const float*)d_in[3];
    const float* lt = (const float*)d_in[4];
    float* out = (float*)d_out;

    int B = in_sizes[1];                       // token_sizes count
    int T = in_sizes[0] / (B * TAGS);          // C == 1

    crf_logz_kernel<<<B, TAGS>>>(em, ts, tr, hd, lt, out, T);
}

// round 12
// speedup vs baseline: 1.1391x; 1.1391x over previous
#include <cuda_runtime.h>
#include <cuda_bf16.h>

#define TAGS 128
typedef __nv_bfloat162 bf2;

__global__ void __launch_bounds__(TAGS, 1) crf_logz_kernel(
    const float* __restrict__ emissions,     // [B, T, 1, TAGS]
    const int*   __restrict__ token_sizes,   // [B]
    const float* __restrict__ transitions,   // [1, 1, TAGS, TAGS]
    const float* __restrict__ head_t,        // [1, 1, TAGS]
    const float* __restrict__ last_t,        // [1, 1, TAGS]
    float*       __restrict__ out,           // [B, 1]
    int T)
{
    __shared__ __align__(16) __nv_bfloat16 pbuf[2][TAGS];
    __shared__ float wsum[4];

    const int n = threadIdx.x;      // output tag owned by this thread
    const int b = blockIdx.x;       // batch element owned by this CTA
    const int len = token_sizes[b];
    const int Tm1 = T - 1;
    const float* emb = emissions + (size_t)b * T * TAGS;

    // exp(transitions) column n as bf16x2 pairs: T2[i] = (T[2i,n], T[2i+1,n]).
    bf2 T2[TAGS / 2];
#pragma unroll
    for (int i = 0; i < TAGS / 2; ++i)
        T2[i] = __floats2bfloat162_rn(__expf(transitions[(2 * i    ) * TAGS + n]),
                                      __expf(transitions[(2 * i + 1) * TAGS + n]));

    // alpha_0 = head + emissions[0]  ->  p = exp(alpha)  (bf16 storage)
    pbuf[0][n] = __float2bfloat16(__expf(head_t[n] + emb[n]));
    int etot = 0;        // exact integer sum of stripped binary exponents
    int fb = 0;          // live buffer for the tail bookkeeping

// One recurrence step, compile-time SRC/DST (static smem addressing).
// 64 HFMA2 (rt=2) = 128 cyc fma pacing; 2 accumulators (reissue spacing
// 4 cyc = HFMA2 lat, stall-free) -> 1-level reduce. Scale applied before
// the lo/hi fold. p[0]'s exponent comes from the first matvec load.
// ALL prefetch work sits BEFORE the __syncthreads (overlaps arrival skew);
// R11 showed anything placed after the barrier lands on the serial path.
#define STEP(SRC, DST, EV) do {                                            \
    __syncthreads();                                                       \
    const uint4* _pd = reinterpret_cast<const uint4*>(&pbuf[SRC][0]);      \
    uint4 _q0 = _pd[0];                                                    \
    int _e = (int)((_q0.x >> 7) & 255) - 127;      /* bf16 exp of p[0] */  \
    float _sc = __int_as_float((127 - _e) << 23);                          \
    bf2 _Es = __float2bfloat162_rn((EV) * _sc);                            \
    bf2 _h0 = __float2bfloat162_rn(0.0f);                                  \
    bf2 _h1 = _h0;                                                         \
    _h0 = __hfma2(*reinterpret_cast<bf2*>(&_q0.x), T2[0], _h0);            \
    _h1 = __hfma2(*reinterpret_cast<bf2*>(&_q0.y), T2[1], _h1);            \
    _h0 = __hfma2(*reinterpret_cast<bf2*>(&_q0.z), T2[2], _h0);            \
    _h1 = __hfma2(*reinterpret_cast<bf2*>(&_q0.w), T2[3], _h1);            \
    _Pragma("unroll")                                                      \
    for (int _i = 1; _i < 16; ++_i) {                                      \
        uint4 _q = _pd[_i];                        /* 8 p-halves */        \
        _h0 = __hfma2(*reinterpret_cast<bf2*>(&_q.x), T2[4 * _i    ], _h0);\
        _h1 = __hfma2(*reinterpret_cast<bf2*>(&_q.y), T2[4 * _i + 1], _h1);\
        _h0 = __hfma2(*reinterpret_cast<bf2*>(&_q.z), T2[4 * _i + 2], _h0);\
        _h1 = __hfma2(*reinterpret_cast<bf2*>(&_q.w), T2[4 * _i + 3], _h1);\
    }                                                                      \
    bf2 _s = __hadd2(_h0, _h1);                                            \
    bf2 _v = __hmul2(_s, _Es);                     /* scale both lanes */  \
    bf2 _pn = __hadd2(_v, __lowhigh2highlow(_v));  /* lo+hi fold */        \
    pbuf[DST][n] = __low2bfloat16(_pn);                                    \
    etot += _e;                                                            \
} while (0)

    // Two-stage emission prefetch with PER-SLOT refresh (correct ordering:
    // E_k is consumed at slot k, then refreshed from Q_k right after -- 4
    // steps before its next use; Q_k reloaded 8 steps ahead).
    int t = 1;
    float E0 = __expf(emb[min(1, Tm1) * TAGS + n]);     // steps t..t+3
    float E1 = __expf(emb[min(2, Tm1) * TAGS + n]);
    float E2 = __expf(emb[min(3, Tm1) * TAGS + n]);
    float E3 = __expf(emb[min(4, Tm1) * TAGS + n]);
    float Q0 = emb[min(5, Tm1) * TAGS + n];             // raw, steps t+4..t+7
    float Q1 = emb[min(6, Tm1) * TAGS + n];
    float Q2 = emb[min(7, Tm1) * TAGS + n];
    float Q3 = emb[min(8, Tm1) * TAGS + n];

    // Fast loop: t+12 <= len implies prefetch rows t+8..t+11 < T: no clamps.
    for (; t + 12 <= len; t += 4) {
        const float* ep = emb + (size_t)(t + 8) * TAGS + n;
        float R0 = ep[0];
        STEP(0, 1, E0);
        float R1 = ep[TAGS];
        E0 = __expf(Q0); Q0 = R0;           // pre-barrier of next step
        STEP(1, 0, E1);
        float R2 = ep[2 * TAGS];
        E1 = __expf(Q1); Q1 = R1;
        STEP(0, 1, E2);
        float R3 = ep[3 * TAGS];
        E2 = __expf(Q2); Q2 = R2;
        STEP(1, 0, E3);
        E3 = __expf(Q3); Q3 = R3;
    }
    // Clamped boundary loop (<= 2 iterations).
    for (; t + 4 <= len; t += 4) {
        int tp = t + 8;
        float R0 = emb[min(tp,     Tm1) * TAGS + n];
        STEP(0, 1, E0);
        float R1 = emb[min(tp + 1, Tm1) * TAGS + n];
        E0 = __expf(Q0); Q0 = R0;
        STEP(1, 0, E1);
        float R2 = emb[min(tp + 2, Tm1) * TAGS + n];
        E1 = __expf(Q1); Q1 = R1;
        STEP(0, 1, E2);
        float R3 = emb[min(tp + 3, Tm1) * TAGS + n];
        E2 = __expf(Q2); Q2 = R2;
        STEP(1, 0, E3);
        E3 = __expf(Q3); Q3 = R3;
    }
    // Tail (0-3 steps); E0..E2 hold exp(em[t..t+2]) by the invariant above.
    if (t < len) { STEP(0, 1, E0); fb = 1; ++t; }
    if (t < len) { STEP(1, 0, E1); fb = 0; ++t; }
    if (t < len) { STEP(0, 1, E2); fb = 1; ++t; }

    // Finalize: out[b] = etot*ln2 + log( sum_n p[n] * exp(last[n]) )  (fp32)
    __syncthreads();
    float v = __bfloat162float(pbuf[fb][n]) * __expf(last_t[n]);
#pragma unroll
    for (int sft = 16; sft > 0; sft >>= 1)
        v += __shfl_xor_sync(0xffffffffu, v, sft);
    if ((n & 31) == 0) wsum[n >> 5] = v;
    __syncthreads();
    if (n == 0)
        out[b] = (float)((double)etot * 0.6931471805599453 +
                         (double)__logf(wsum[0] + wsum[1] + wsum[2] + wsum[3]));
}

extern "C" void kernel_launch(void* const* d_in, const int* in_sizes, int n_in,
                              void* d_out, int out_size) {
    const float* em = (const float*)d_in[0];
    const int*   ts = (const int*)  d_in[1];
    const float* tr = (const float*)d_in[2];
    const float* hd = (const float*)d_in[3];
    const float* lt = (const float*)d_in[4];
    float* out = (float*)d_out;

    int B = in_sizes[1];                       // token_sizes count
    int T = in_sizes[0] / (B * TAGS);          // C == 1

    crf_logz_kernel<<<B, TAGS>>>(em, ts, tr, hd, lt, out, T);
}

// round 13
// speedup vs baseline: 1.1628x; 1.0208x over previous
#include <cuda_runtime.h>
#include <cuda_bf16.h>

#define TAGS 128
typedef __nv_bfloat162 bf2;

__global__ void __launch_bounds__(TAGS, 1) crf_logz_kernel(
    const float* __restrict__ emissions,     // [B, T, 1, TAGS]
    const int*   __restrict__ token_sizes,   // [B]
    const float* __restrict__ transitions,   // [1, 1, TAGS, TAGS]
    const float* __restrict__ head_t,        // [1, 1, TAGS]
    const float* __restrict__ last_t,        // [1, 1, TAGS]
    float*       __restrict__ out,           // [B, 1]
    int T)
{
    __shared__ __align__(16) __nv_bfloat16 pbuf[2][TAGS];
    __shared__ float wsum[4];

    const int n = threadIdx.x;      // output tag owned by this thread
    const int b = blockIdx.x;       // batch element owned by this CTA
    const int len = token_sizes[b];
    const int Tm1 = T - 1;
    const float* emb = emissions + (size_t)b * T * TAGS;

    // exp(transitions) column n as bf16x2 pairs: T2[i] = (T[2i,n], T[2i+1,n]).
    bf2 T2[TAGS / 2];
#pragma unroll
    for (int i = 0; i < TAGS / 2; ++i)
        T2[i] = __floats2bfloat162_rn(__expf(transitions[(2 * i    ) * TAGS + n]),
                                      __expf(transitions[(2 * i + 1) * TAGS + n]));

    // alpha_0 = head + emissions[0]  ->  p = exp(alpha)  (bf16 storage)
    pbuf[0][n] = __float2bfloat16(__expf(head_t[n] + emb[n]));
    int etot = 0;        // exact integer sum of stripped binary exponents
    int fb = 0;          // live buffer for the tail bookkeeping

// One recurrence step, compile-time SRC/DST (static smem addressing).
// 64 HFMA2 (rt=2) = 128 cyc fma pacing; 2 accumulators (reissue spacing
// 4 cyc = HFMA2 lat, stall-free) -> 1-level reduce. Short tail:
//   HADD2(accs) -> HADD2 with half-lane selectors (lo+hi fold, no PRMT)
//   -> scalar HMUL by pre-converted bf16 scale -> STS.b16
// p[0]'s exponent comes from the first matvec load; the scale conversion
// to bf16 runs during the matvec (off the serial path).
// ALL prefetch work sits BEFORE the __syncthreads (overlaps arrival skew).
#define STEP(SRC, DST, EV) do {                                            \
    __syncthreads();                                                       \
    const uint4* _pd = reinterpret_cast<const uint4*>(&pbuf[SRC][0]);      \
    uint4 _q0 = _pd[0];                                                    \
    int _e = (int)((_q0.x >> 7) & 255) - 127;      /* bf16 exp of p[0] */  \
    float _sc = __int_as_float((127 - _e) << 23);                          \
    __nv_bfloat16 _Esb = __float2bfloat16((EV) * _sc);                     \
    bf2 _h0 = __float2bfloat162_rn(0.0f);                                  \
    bf2 _h1 = _h0;                                                         \
    _h0 = __hfma2(*reinterpret_cast<bf2*>(&_q0.x), T2[0], _h0);            \
    _h1 = __hfma2(*reinterpret_cast<bf2*>(&_q0.y), T2[1], _h1);            \
    _h0 = __hfma2(*reinterpret_cast<bf2*>(&_q0.z), T2[2], _h0);            \
    _h1 = __hfma2(*reinterpret_cast<bf2*>(&_q0.w), T2[3], _h1);            \
    _Pragma("unroll")                                                      \
    for (int _i = 1; _i < 16; ++_i) {                                      \
        uint4 _q = _pd[_i];                        /* 8 p-halves */        \
        _h0 = __hfma2(*reinterpret_cast<bf2*>(&_q.x), T2[4 * _i    ], _h0);\
        _h1 = __hfma2(*reinterpret_cast<bf2*>(&_q.y), T2[4 * _i + 1], _h1);\
        _h0 = __hfma2(*reinterpret_cast<bf2*>(&_q.z), T2[4 * _i + 2], _h0);\
        _h1 = __hfma2(*reinterpret_cast<bf2*>(&_q.w), T2[4 * _i + 3], _h1);\
    }                                                                      \
    bf2 _s = __hadd2(_h0, _h1);                                            \
    __nv_bfloat16 _f = __hadd(__low2bfloat16(_s), __high2bfloat16(_s));    \
    pbuf[DST][n] = __hmul(_f, _Esb);                                       \
    etot += _e;                                                            \
} while (0)

    // Two-stage emission prefetch with per-slot refresh:
    //   E_k consumed at slot k, refreshed from Q_k right after (4 steps
    //   before next use); Q_k reloaded 8 steps ahead.
    int t = 1;
    float E0 = __expf(emb[min(1, Tm1) * TAGS + n]);     // steps t..t+3
    float E1 = __expf(emb[min(2, Tm1) * TAGS + n]);
    float E2 = __expf(emb[min(3, Tm1) * TAGS + n]);
    float E3 = __expf(emb[min(4, Tm1) * TAGS + n]);
    float Q0 = emb[min(5, Tm1) * TAGS + n];             // raw, steps t+4..t+7
    float Q1 = emb[min(6, Tm1) * TAGS + n];
    float Q2 = emb[min(7, Tm1) * TAGS + n];
    float Q3 = emb[min(8, Tm1) * TAGS + n];

    // Fast loop: t+12 <= len implies prefetch rows t+8..t+11 < T: no clamps.
    for (; t + 12 <= len; t += 4) {
        const float* ep = emb + (size_t)(t + 8) * TAGS + n;
        float R0 = ep[0];
        STEP(0, 1, E0);
        float R1 = ep[TAGS];
        E0 = __expf(Q0); Q0 = R0;           // pre-barrier of next step
        STEP(1, 0, E1);
        float R2 = ep[2 * TAGS];
        E1 = __expf(Q1); Q1 = R1;
        STEP(0, 1, E2);
        float R3 = ep[3 * TAGS];
        E2 = __expf(Q2); Q2 = R2;
        STEP(1, 0, E3);
        E3 = __expf(Q3); Q3 = R3;
    }
    // Clamped boundary loop (<= 2 iterations).
    for (; t + 4 <= len; t += 4) {
        int tp = t + 8;
        float R0 = emb[min(tp,     Tm1) * TAGS + n];
        STEP(0, 1, E0);
        float R1 = emb[min(tp + 1, Tm1) * TAGS + n];
        E0 = __expf(Q0); Q0 = R0;
        STEP(1, 0, E1);
        float R2 = emb[min(tp + 2, Tm1) * TAGS + n];
        E1 = __expf(Q1); Q1 = R1;
        STEP(0, 1, E2);
        float R3 = emb[min(tp + 3, Tm1) * TAGS + n];
        E2 = __expf(Q2); Q2 = R2;
        STEP(1, 0, E3);
        E3 = __expf(Q3); Q3 = R3;
    }
    // Tail (0-3 steps); E0..E2 hold exp(em[t..t+2]) by the invariant above.
    if (t < len) { STEP(0, 1, E0); fb = 1; ++t; }
    if (t < len) { STEP(1, 0, E1); fb = 0; ++t; }
    if (t < len) { STEP(0, 1, E2); fb = 1; ++t; }

    // Finalize: out[b] = etot*ln2 + log( sum_n p[n] * exp(last[n]) )  (fp32)
    __syncthreads();
    float v = __bfloat162float(pbuf[fb][n]) * __expf(last_t[n]);
#pragma unroll
    for (int sft = 16; sft > 0; sft >>= 1)
        v += __shfl_xor_sync(0xffffffffu, v, sft);
    if ((n & 31) == 0) wsum[n >> 5] = v;
    __syncthreads();
    if (n == 0)
        out[b] = (float)((double)etot * 0.6931471805599453 +
                         (double)__logf(wsum[0] + wsum[1] + wsum[2] + wsum[3]));
}

extern "C" void kernel_launch(void* const* d_in, const int* in_sizes, int n_in,
                              void* d_out, int out_size) {
    const float* em = (const float*)d_in[0];
    const int*   ts = (const int*)  d_in[1];
    const float* tr = (const float*)d_in[2];
    const float* hd = (const float*)d_in[3];
    const float* lt = (const float*)d_in[4];
    float* out = (float*)d_out;

    int B = in_sizes[1];                       // token_sizes count
    int T = in_sizes[0] / (B * TAGS);          // C == 1

    crf_logz_kernel<<<B, TAGS>>>(em, ts, tr, hd, lt, out, T);
}